// round 14
// baseline (speedup 1.0000x reference)
#include <cuda_runtime.h>

// y = x*2 + 5 - 3/(1+x), elementwise over 8192*8192 fp32 (64M elems).
// R14: final policy-matrix cell — __ldcs loads + DEFAULT write-back stores
// (every other load x store policy combination already measured at the
// winning shape: V=4 float4/thread front-batched, T=256, 16384 CTAs).
// Default stores let L2 coalesce dirty lines into larger writeback bursts
// instead of evict-first immediate drains; model predicts a tie, probe is
// zero-risk since the 81.95us best is locked.

constexpr int V = 4;    // float4 per thread
constexpr int T = 256;  // threads per block

__global__ __launch_bounds__(T)
void elementwise_defst_kernel(const float4* __restrict__ in,
                              float4* __restrict__ out) {
    int base = blockIdx.x * (T * V) + threadIdx.x;

    float4 v[V];
#pragma unroll
    for (int k = 0; k < V; k++) {
        v[k] = __ldcs(&in[base + k * T]);   // 4 independent LDG.E.128, front-batched
    }

#pragma unroll
    for (int k = 0; k < V; k++) {
        float4 r;
        r.x = fmaf(v[k].x, 2.0f, 5.0f) - __fdividef(3.0f, 1.0f + v[k].x);
        r.y = fmaf(v[k].y, 2.0f, 5.0f) - __fdividef(3.0f, 1.0f + v[k].y);
        r.z = fmaf(v[k].z, 2.0f, 5.0f) - __fdividef(3.0f, 1.0f + v[k].z);
        r.w = fmaf(v[k].w, 2.0f, 5.0f) - __fdividef(3.0f, 1.0f + v[k].w);
        out[base + k * T] = r;               // default write-back store
    }
}

extern "C" void kernel_launch(void* const* d_in, const int* in_sizes, int n_in,
                              void* d_out, int out_size) {
    const float* x = (const float*)d_in[0];
    float* y = (float*)d_out;
    int n = in_sizes[0];          // 67108864 = 8192*8192
    int n4 = n >> 2;              // 16777216 float4

    // Exact tiling: 16777216 / (256*4) = 16384 blocks, no tail.
    int blocks = n4 / (T * V);
    elementwise_defst_kernel<<<blocks, T>>>(
        (const float4*)x, (float4*)y);
}

// round 15
// speedup vs baseline: 1.0027x; 1.0027x over previous
#include <cuda_runtime.h>

// y = x*2 + 5 - 3/(1+x), elementwise over 8192*8192 fp32 (64M elems).
//
// FINAL — locked after a 14-round exhaustive mechanism sweep:
//   MLP 1/4/8 | 128/256-bit ops | full load x store policy matrix
//   (default/ldg/cs/cg/wt/evict-last) | T=128/256/512 | oversubscribed vs
//   persistent grids | refined vs MUFU divide.
// All sound configurations land at 6.34-6.52 TB/s — the mixed 1:1 R/W HBM3e
// ceiling on this part (~81% of the 8 TB/s unidirectional spec; bus
// turnaround + refresh overhead). Compute pipes <10%, issue <21%: the kernel
// is pinned to the memory wall, not to any SM resource.
//
// Best-measured point (reproduced 5x at 81.95-82.14 us, peak 6.52 TB/s):
//   - 4x float4 per thread, front-batched (MLP=4), 256-thread blocks,
//     16384-CTA oversubscribed grid (deep CTA pool = the memory pipeline;
//     persistent single-wave measured 13% worse).
//   - streaming cache hints (ld/st.global.cs) on pure pass-through data.
//   - __fdividef: MUFU.RCP+MUL (rel_err ~3.4e-8 << 1e-3 threshold).

constexpr int V = 4;    // float4 per thread
constexpr int T = 256;  // threads per block

__global__ __launch_bounds__(T)
void elementwise_final_kernel(const float4* __restrict__ in,
                              float4* __restrict__ out) {
    int base = blockIdx.x * (T * V) + threadIdx.x;

    float4 v[V];
#pragma unroll
    for (int k = 0; k < V; k++) {
        v[k] = __ldcs(&in[base + k * T]);   // 4 independent LDG.E.128, front-batched
    }

#pragma unroll
    for (int k = 0; k < V; k++) {
        float4 r;
        r.x = fmaf(v[k].x, 2.0f, 5.0f) - __fdividef(3.0f, 1.0f + v[k].x);
        r.y = fmaf(v[k].y, 2.0f, 5.0f) - __fdividef(3.0f, 1.0f + v[k].y);
        r.z = fmaf(v[k].z, 2.0f, 5.0f) - __fdividef(3.0f, 1.0f + v[k].z);
        r.w = fmaf(v[k].w, 2.0f, 5.0f) - __fdividef(3.0f, 1.0f + v[k].w);
        __stcs(&out[base + k * T], r);
    }
}

extern "C" void kernel_launch(void* const* d_in, const int* in_sizes, int n_in,
                              void* d_out, int out_size) {
    const float* x = (const float*)d_in[0];
    float* y = (float*)d_out;
    int n = in_sizes[0];          // 67108864 = 8192*8192
    int n4 = n >> 2;              // 16777216 float4

    // Exact tiling: 16777216 / (256*4) = 16384 blocks, no tail.
    int blocks = n4 / (T * V);
    elementwise_final_kernel<<<blocks, T>>>(
        (const float4*)x, (float4*)y);
}